// round 1
// baseline (speedup 1.0000x reference)
#include <cuda_runtime.h>
#include <math.h>

#define NN 100000
#define NE 1600000
#define FD 128

// ---------------- scratch (device globals; no allocation allowed) -------------
__device__ float g_bufs[6][NN * FD];   // 0..5 generic [NN,128] buffers (~307MB)
__device__ float g_Hc[NN * 10];        // classifier pre-agg
__device__ int   g_cnt[2][NN];         // in-degree counts per graph
__device__ int   g_off[2][NN];         // CSR exclusive offsets
__device__ int   g_cur[2][NN];         // fill cursors
__device__ int   g_csr[2][NE];         // CSR src lists
__device__ float g_dis[2][NN];         // rsqrt(deg)
__device__ float g_invdeg[2][NN];      // 1/deg
__device__ int   g_bsum[2][128];       // scan block sums

// ---------------- degree / CSR build ------------------------------------------
__global__ void k_zero_cnt() {
    int i = blockIdx.x * blockDim.x + threadIdx.x;
    if (i < NN) { g_cnt[0][i] = 0; g_cnt[1][i] = 0; }
}

__global__ void k_count(const int* __restrict__ ei, int E, int g) {
    int e = blockIdx.x * blockDim.x + threadIdx.x;
    if (e < E) atomicAdd(&g_cnt[g][ei[E + e]], 1);
}

__global__ void k_deg(int g) {
    int i = blockIdx.x * blockDim.x + threadIdx.x;
    if (i < NN) {
        float d = (float)g_cnt[g][i] + 1.0f;
        g_dis[g][i] = rsqrtf(d);
        g_invdeg[g][i] = 1.0f / d;
    }
}

__global__ void k_scan1(int g) {   // per-block exclusive scan, 1024 elems/block
    __shared__ int s[1024];
    int tid = threadIdx.x;
    int i = blockIdx.x * 1024 + tid;
    int v = (i < NN) ? g_cnt[g][i] : 0;
    s[tid] = v;
    __syncthreads();
    for (int off = 1; off < 1024; off <<= 1) {
        int t = (tid >= off) ? s[tid - off] : 0;
        __syncthreads();
        s[tid] += t;
        __syncthreads();
    }
    if (i < NN) g_off[g][i] = s[tid] - v;
    if (tid == 1023) g_bsum[g][blockIdx.x] = s[1023];
}

__global__ void k_scan2(int g, int nb) {   // tiny serial scan of block sums
    if (threadIdx.x == 0 && blockIdx.x == 0) {
        int a = 0;
        for (int b = 0; b < nb; b++) { int t = g_bsum[g][b]; g_bsum[g][b] = a; a += t; }
    }
}

__global__ void k_scan3(int g) {
    int i = blockIdx.x * blockDim.x + threadIdx.x;
    if (i < NN) {
        int o = g_off[g][i] + g_bsum[g][i >> 10];
        g_off[g][i] = o;
        g_cur[g][i] = o;
    }
}

__global__ void k_fill(const int* __restrict__ ei, int E, int g) {
    int e = blockIdx.x * blockDim.x + threadIdx.x;
    if (e < E) {
        int s = ei[e];
        int d = ei[E + e];
        int p = atomicAdd(&g_cur[g][d], 1);
        g_csr[g][p] = s;
    }
}

// ---------------- GEMM: [M,K] x [K,128] -> g_bufs[outid] ----------------------
// 64-row output tile per block; 256 threads; thread = (warp=ty rows ty+8r, cols 4*tx)
__global__ __launch_bounds__(256) void k_gemm_n128(
    const float* __restrict__ Xext, int xid, const float* __restrict__ W,
    int outid, const float* __restrict__ bias, int relu, int M, int K)
{
    const float* __restrict__ X = (xid >= 0) ? g_bufs[xid] : Xext;
    float* __restrict__ O = g_bufs[outid];
    __shared__ float sX[64 * 64];
    __shared__ float sW[64 * 128];
    int tid = threadIdx.x;
    int tx = tid & 31;
    int ty = tid >> 5;
    int m0 = blockIdx.x * 64;

    float4 acc[8];
#pragma unroll
    for (int r = 0; r < 8; r++) acc[r] = make_float4(0.f, 0.f, 0.f, 0.f);

    for (int kc = 0; kc < K; kc += 64) {
#pragma unroll
        for (int j = 0; j < 4; j++) {            // X tile 64x64
            int idx = tid + j * 256;
            int r = idx >> 4;
            int c = (idx & 15) * 4;
            int gm = m0 + r;
            float4 v = make_float4(0.f, 0.f, 0.f, 0.f);
            if (gm < M) v = *(const float4*)&X[(long)gm * K + kc + c];
            *(float4*)&sX[r * 64 + c] = v;
        }
#pragma unroll
        for (int j = 0; j < 8; j++) {            // W tile 64x128
            int idx = tid + j * 256;
            int r = idx >> 5;
            int c = (idx & 31) * 4;
            *(float4*)&sW[r * 128 + c] = *(const float4*)&W[(long)(kc + r) * 128 + c];
        }
        __syncthreads();
#pragma unroll 8
        for (int k = 0; k < 64; k++) {
            float4 w = *(const float4*)&sW[k * 128 + tx * 4];
#pragma unroll
            for (int r = 0; r < 8; r++) {
                float a = sX[(ty + 8 * r) * 64 + k];
                acc[r].x = fmaf(a, w.x, acc[r].x);
                acc[r].y = fmaf(a, w.y, acc[r].y);
                acc[r].z = fmaf(a, w.z, acc[r].z);
                acc[r].w = fmaf(a, w.w, acc[r].w);
            }
        }
        __syncthreads();
    }

    float4 bv = make_float4(0.f, 0.f, 0.f, 0.f);
    if (bias) bv = *(const float4*)&bias[tx * 4];
#pragma unroll
    for (int r = 0; r < 8; r++) {
        int m = m0 + ty + 8 * r;
        if (m < M) {
            float4 o;
            o.x = acc[r].x + bv.x; o.y = acc[r].y + bv.y;
            o.z = acc[r].z + bv.z; o.w = acc[r].w + bv.w;
            if (relu) {
                o.x = fmaxf(o.x, 0.f); o.y = fmaxf(o.y, 0.f);
                o.z = fmaxf(o.z, 0.f); o.w = fmaxf(o.w, 0.f);
            }
            *(float4*)&O[(long)m * 128 + tx * 4] = o;
        }
    }
}

// ---------------- GCN aggregation, width 128 (warp per node) ------------------
// out[i] = dis[i]*sum_e dis[src]*H[map(src)] + invdeg[i]*H[map(i)] + b   (opt relu)
__global__ void k_agg128(int srcid, int dstid, int g, const float* __restrict__ bias,
                         const int* __restrict__ map, int relu, int M)
{
    int lane = threadIdx.x & 31;
    int i = (blockIdx.x * blockDim.x + threadIdx.x) >> 5;
    if (i >= M) return;
    const float4* __restrict__ H4 = (const float4*)g_bufs[srcid];
    float4* __restrict__ O4 = (float4*)g_bufs[dstid];
    const float* __restrict__ dis = g_dis[g];
    const int* __restrict__ csr = g_csr[g];
    int s0 = g_off[g][i];
    int s1 = s0 + g_cnt[g][i];

    float4 acc = make_float4(0.f, 0.f, 0.f, 0.f);
    for (int e = s0; e < s1; e++) {
        int s = csr[e];
        float c = dis[s];
        int r = map ? map[s] : s;
        float4 h = H4[r * 32 + lane];
        acc.x = fmaf(c, h.x, acc.x);
        acc.y = fmaf(c, h.y, acc.y);
        acc.z = fmaf(c, h.z, acc.z);
        acc.w = fmaf(c, h.w, acc.w);
    }
    int rs = map ? map[i] : i;
    float4 hs = H4[rs * 32 + lane];
    float di = dis[i];
    float vd = g_invdeg[g][i];
    float4 b4 = ((const float4*)bias)[lane];
    float4 o;
    o.x = fmaf(di, acc.x, fmaf(vd, hs.x, b4.x));
    o.y = fmaf(di, acc.y, fmaf(vd, hs.y, b4.y));
    o.z = fmaf(di, acc.z, fmaf(vd, hs.z, b4.z));
    o.w = fmaf(di, acc.w, fmaf(vd, hs.w, b4.w));
    if (relu) {
        o.x = fmaxf(o.x, 0.f); o.y = fmaxf(o.y, 0.f);
        o.z = fmaxf(o.z, 0.f); o.w = fmaxf(o.w, 0.f);
    }
    O4[i * 32 + lane] = o;
}

// ---------------- classifier GEMM [NN,128]x[128,10] ---------------------------
__global__ __launch_bounds__(320) void k_gemm_n10(int xid, const float* __restrict__ W)
{
    __shared__ float sW[128 * 10];
    __shared__ float sX[32 * 128];
    int tid = threadIdx.x;
    const float* __restrict__ X = g_bufs[xid];
    for (int j = tid; j < 1280; j += 320) sW[j] = W[j];
    int m0 = blockIdx.x * 32;
    for (int j = tid; j < 32 * 128; j += 320) {
        int r = j >> 7, c = j & 127;
        int gm = m0 + r;
        sX[j] = (gm < NN) ? X[(long)gm * 128 + c] : 0.f;
    }
    __syncthreads();
    int lr = tid / 10, c = tid % 10;
    if (lr >= 32) return;
    int gm = m0 + lr;
    float acc = 0.f;
#pragma unroll 8
    for (int k = 0; k < 128; k++) acc = fmaf(sX[lr * 128 + k], sW[k * 10 + c], acc);
    if (gm < NN) g_Hc[gm * 10 + c] = acc;
}

// ---------------- classifier aggregation, width 10, into out[:,0:10] ----------
__global__ void k_agg10(float* __restrict__ out, const float* __restrict__ bc, int g, int M)
{
    int lane = threadIdx.x & 31;
    int i = (blockIdx.x * blockDim.x + threadIdx.x) >> 5;
    if (i >= M) return;
    const float* __restrict__ dis = g_dis[g];
    const int* __restrict__ csr = g_csr[g];
    int s0 = g_off[g][i];
    int s1 = s0 + g_cnt[g][i];
    float acc = 0.f;
    for (int e = s0; e < s1; e++) {
        int s = csr[e];
        float c = dis[s];
        float h = (lane < 10) ? g_Hc[s * 10 + lane] : 0.f;
        acc = fmaf(c, h, acc);
    }
    if (lane < 10) {
        float o = dis[i] * acc + g_invdeg[g][i] * g_Hc[i * 10 + lane] + bc[lane];
        out[(long)i * 12 + lane] = o;
    }
}

// ---------------- bilinear scores: sigmoid(rowdot(T, e2)) ---------------------
__global__ void k_score(int tbuf, int abuf, int bbuf, float* __restrict__ out, int M)
{
    int lane = threadIdx.x & 31;
    int i = (blockIdx.x * blockDim.x + threadIdx.x) >> 5;
    if (i >= M) return;
    float4 t = ((const float4*)g_bufs[tbuf])[i * 32 + lane];
    float4 a = ((const float4*)g_bufs[abuf])[i * 32 + lane];
    float4 b = ((const float4*)g_bufs[bbuf])[i * 32 + lane];
    float s1 = t.x * a.x + t.y * a.y + t.z * a.z + t.w * a.w;
    float s2 = t.x * b.x + t.y * b.y + t.z * b.z + t.w * b.w;
#pragma unroll
    for (int o = 16; o; o >>= 1) {
        s1 += __shfl_xor_sync(0xffffffffu, s1, o);
        s2 += __shfl_xor_sync(0xffffffffu, s2, o);
    }
    if (lane == 0) {
        out[(long)i * 12 + 10] = 1.f / (1.f + expf(-s1));
        out[(long)i * 12 + 11] = 1.f / (1.f + expf(-s2));
    }
}

// ---------------- launch ------------------------------------------------------
extern "C" void kernel_launch(void* const* d_in, const int* in_sizes, int n_in,
                              void* d_out, int out_size)
{
    const float* x    = (const float*)d_in[0];
    const int*   ei   = (const int*)d_in[1];
    const int*   eih  = (const int*)d_in[2];
    const int*   perm = (const int*)d_in[4];
    const float* W1 = (const float*)d_in[5];
    const float* b1 = (const float*)d_in[6];
    const float* W2 = (const float*)d_in[7];
    const float* b2 = (const float*)d_in[8];
    const float* W3 = (const float*)d_in[9];
    const float* b3 = (const float*)d_in[10];
    const float* M1 = (const float*)d_in[11];
    const float* mb1 = (const float*)d_in[12];
    const float* M2 = (const float*)d_in[13];
    const float* mb2 = (const float*)d_in[14];
    const float* Wc = (const float*)d_in[15];
    const float* bc = (const float*)d_in[16];
    const float* Wd = (const float*)d_in[17];
    float* out = (float*)d_out;

    int M = in_sizes[0] / 512;   // 100000
    int E = in_sizes[1] / 2;     // 1600000

    int nb_scan = (NN + 1023) / 1024;  // 98
    int GB = (M + 63) / 64;            // GEMM blocks
    int AB = (M + 7) / 8;              // agg blocks (8 warps/block)

    // --- CSR + degrees for both graphs ---
    k_zero_cnt<<<(NN + 255) / 256, 256>>>();
    k_count<<<(E + 255) / 256, 256>>>(ei, E, 0);
    k_count<<<(E + 255) / 256, 256>>>(eih, E, 1);
    k_deg<<<(NN + 255) / 256, 256>>>(0);
    k_deg<<<(NN + 255) / 256, 256>>>(1);
    k_scan1<<<nb_scan, 1024>>>(0);
    k_scan1<<<nb_scan, 1024>>>(1);
    k_scan2<<<1, 32>>>(0, nb_scan);
    k_scan2<<<1, 32>>>(1, nb_scan);
    k_scan3<<<(NN + 255) / 256, 256>>>(0);
    k_scan3<<<(NN + 255) / 256, 256>>>(1);
    k_fill<<<(E + 255) / 256, 256>>>(ei, E, 0);
    k_fill<<<(E + 255) / 256, 256>>>(eih, E, 1);

    // --- H = x @ W1 (shared by normal + permuted branch: x[perm]@W1 = H[perm]) ---
    k_gemm_n128<<<GB, 256>>>(x, -1, W1, 0, nullptr, 0, M, 512);

    // layer 1: h1 (buf1), h1_bad (buf2) via perm map
    k_agg128<<<AB, 256>>>(0, 1, 0, b1, nullptr, 1, M);
    k_agg128<<<AB, 256>>>(0, 2, 0, b1, perm, 1, M);

    // layer 2: embed1 (buf4), embed1_bad (buf5)
    k_gemm_n128<<<GB, 256>>>(nullptr, 1, W2, 3, nullptr, 0, M, 128);
    k_agg128<<<AB, 256>>>(3, 4, 0, b2, nullptr, 1, M);
    k_gemm_n128<<<GB, 256>>>(nullptr, 2, W2, 3, nullptr, 0, M, 128);
    k_agg128<<<AB, 256>>>(3, 5, 0, b2, nullptr, 1, M);

    // encoder2 (hop graph, no relu): embed2 (buf1), embed2_bad (buf2)
    k_gemm_n128<<<GB, 256>>>(nullptr, 4, W3, 0, nullptr, 0, M, 128);
    k_agg128<<<AB, 256>>>(0, 1, 1, b3, nullptr, 0, M);
    k_gemm_n128<<<GB, 256>>>(nullptr, 5, W3, 0, nullptr, 0, M, 128);
    k_agg128<<<AB, 256>>>(0, 2, 1, b3, nullptr, 0, M);

    // encoder3 MLP: embed3 = relu(embed1@M1+mb1)@M2+mb2  (buf0 tmp -> buf3)
    k_gemm_n128<<<GB, 256>>>(nullptr, 4, M1, 0, mb1, 1, M, 128);
    k_gemm_n128<<<GB, 256>>>(nullptr, 0, M2, 3, mb2, 0, M, 128);

    // bilinear: T = embed3 @ Wd (buf5), shared by both scores
    k_gemm_n128<<<GB, 256>>>(nullptr, 3, Wd, 5, nullptr, 0, M, 128);
    k_score<<<AB, 256>>>(5, 1, 2, out, M);

    // classifier: gcn(embed1, Wc) -> out[:,0:10]
    k_gemm_n10<<<(M + 31) / 32, 320>>>(4, Wc);
    k_agg10<<<AB, 256>>>(out, bc, 0, M);
}

// round 3
// speedup vs baseline: 1.0212x; 1.0212x over previous
#include <cuda_runtime.h>
#include <math.h>

#define NN 100000
#define NE 1600000
#define FD 128

// ---------------- scratch (device globals; no allocation allowed) -------------
__device__ float g_bufs[6][NN * FD];   // 0..5 generic [NN,128] buffers (~307MB)
__device__ float g_Hc[NN * 10];        // classifier pre-agg
__device__ int   g_cnt[2][NN];         // in-degree counts per graph
__device__ int   g_off[2][NN];         // CSR exclusive offsets
__device__ int   g_cur[2][NN];         // fill cursors
__device__ int   g_csr[2][NE];         // CSR src lists
__device__ float g_dis[2][NN];         // rsqrt(deg)
__device__ float g_invdeg[2][NN];      // 1/deg
__device__ int   g_bsum[2][128];       // scan block sums

// ---------------- degree / CSR build ------------------------------------------
__global__ void k_zero_cnt() {
    int i = blockIdx.x * blockDim.x + threadIdx.x;
    if (i < NN) { g_cnt[0][i] = 0; g_cnt[1][i] = 0; }
}

__global__ void k_count(const int* __restrict__ ei, int E, int g) {
    int e = blockIdx.x * blockDim.x + threadIdx.x;
    if (e < E) atomicAdd(&g_cnt[g][ei[E + e]], 1);
}

__global__ void k_deg(int g) {
    int i = blockIdx.x * blockDim.x + threadIdx.x;
    if (i < NN) {
        float d = (float)g_cnt[g][i] + 1.0f;
        g_dis[g][i] = rsqrtf(d);
        g_invdeg[g][i] = 1.0f / d;
    }
}

__global__ void k_scan1(int g) {   // per-block exclusive scan, 1024 elems/block
    __shared__ int s[1024];
    int tid = threadIdx.x;
    int i = blockIdx.x * 1024 + tid;
    int v = (i < NN) ? g_cnt[g][i] : 0;
    s[tid] = v;
    __syncthreads();
    for (int off = 1; off < 1024; off <<= 1) {
        int t = (tid >= off) ? s[tid - off] : 0;
        __syncthreads();
        s[tid] += t;
        __syncthreads();
    }
    if (i < NN) g_off[g][i] = s[tid] - v;
    if (tid == 1023) g_bsum[g][blockIdx.x] = s[1023];
}

__global__ void k_scan2(int g, int nb) {   // tiny serial scan of block sums
    if (threadIdx.x == 0 && blockIdx.x == 0) {
        int a = 0;
        for (int b = 0; b < nb; b++) { int t = g_bsum[g][b]; g_bsum[g][b] = a; a += t; }
    }
}

__global__ void k_scan3(int g) {
    int i = blockIdx.x * blockDim.x + threadIdx.x;
    if (i < NN) {
        int o = g_off[g][i] + g_bsum[g][i >> 10];
        g_off[g][i] = o;
        g_cur[g][i] = o;
    }
}

__global__ void k_fill(const int* __restrict__ ei, int E, int g) {
    int e = blockIdx.x * blockDim.x + threadIdx.x;
    if (e < E) {
        int s = ei[e];
        int d = ei[E + e];
        int p = atomicAdd(&g_cur[g][d], 1);
        g_csr[g][p] = s;
    }
}

// ---------------- GEMM: [M,K] x [K,128] -> g_bufs[outid] ----------------------
// 128x128 tile / block, 256 threads, 8x8 per thread, packed fma.rn.f32x2 (FFMA2).
// Thread (tx=tid&15, ty=tid>>4): rows m0 + r*16 + ty (r<8),
// cols {tx*4..tx*4+3} and {64+tx*4..67+tx*4}.
#define FMA2(acc, a, b) asm("fma.rn.f32x2 %0, %1, %2, %0;" : "+l"(acc) : "l"(a), "l"(b))

__global__ __launch_bounds__(256, 2) void k_gemm_n128(
    const float* __restrict__ Xext, int xid, const float* __restrict__ W,
    int outid, const float* __restrict__ bias, int relu, int M, int K)
{
    const float* __restrict__ X = (xid >= 0) ? g_bufs[xid] : Xext;
    float* __restrict__ O = g_bufs[outid];
    __shared__ float sX[128 * 36];   // 128 rows x 32 k, stride 36 (bank-safe, 16B-aligned)
    __shared__ float sW[32 * 128];   // 32 k x 128 cols
    int tid = threadIdx.x;
    int tx = tid & 15;
    int ty = tid >> 4;
    int m0 = blockIdx.x * 128;

    unsigned long long acc[8][4];
#pragma unroll
    for (int r = 0; r < 8; r++)
#pragma unroll
        for (int p = 0; p < 4; p++) acc[r][p] = 0ull;

    for (int kc = 0; kc < K; kc += 32) {
#pragma unroll
        for (int j = 0; j < 4; j++) {            // X tile 128x32 (1024 float4)
            int idx = tid + j * 256;
            int r = idx >> 3;
            int c = (idx & 7) * 4;
            int gm = m0 + r;
            float4 v = make_float4(0.f, 0.f, 0.f, 0.f);
            if (gm < M) v = *(const float4*)&X[(long)gm * K + kc + c];
            *(float4*)&sX[r * 36 + c] = v;
        }
#pragma unroll
        for (int j = 0; j < 4; j++) {            // W tile 32x128 (1024 float4)
            int idx = tid + j * 256;
            int r = idx >> 5;
            int c = (idx & 31) * 4;
            *(float4*)&sW[r * 128 + c] = *(const float4*)&W[(long)(kc + r) * 128 + c];
        }
        __syncthreads();
#pragma unroll 8
        for (int k = 0; k < 32; k++) {
            ulonglong2 wa = *(const ulonglong2*)&sW[k * 128 + tx * 4];
            ulonglong2 wb = *(const ulonglong2*)&sW[k * 128 + 64 + tx * 4];
#pragma unroll
            for (int r = 0; r < 8; r++) {
                float a = sX[(r * 16 + ty) * 36 + k];
                unsigned long long ap;
                asm("mov.b64 %0, {%1, %1};" : "=l"(ap) : "r"(__float_as_uint(a)));
                FMA2(acc[r][0], ap, wa.x);
                FMA2(acc[r][1], ap, wa.y);
                FMA2(acc[r][2], ap, wb.x);
                FMA2(acc[r][3], ap, wb.y);
            }
        }
        __syncthreads();
    }

    float bA[4] = {0.f, 0.f, 0.f, 0.f};
    float bB[4] = {0.f, 0.f, 0.f, 0.f};
    if (bias) {
        *(float4*)bA = *(const float4*)&bias[tx * 4];
        *(float4*)bB = *(const float4*)&bias[64 + tx * 4];
    }
#pragma unroll
    for (int r = 0; r < 8; r++) {
        int m = m0 + r * 16 + ty;
        if (m < M) {
            float v[8];
#pragma unroll
            for (int p = 0; p < 4; p++) {
                unsigned int lo, hi;
                asm("mov.b64 {%0, %1}, %2;" : "=r"(lo), "=r"(hi) : "l"(acc[r][p]));
                v[p * 2] = __uint_as_float(lo);
                v[p * 2 + 1] = __uint_as_float(hi);
            }
            float4 oA, oB;
            oA.x = v[0] + bA[0]; oA.y = v[1] + bA[1];
            oA.z = v[2] + bA[2]; oA.w = v[3] + bA[3];
            oB.x = v[4] + bB[0]; oB.y = v[5] + bB[1];
            oB.z = v[6] + bB[2]; oB.w = v[7] + bB[3];
            if (relu) {
                oA.x = fmaxf(oA.x, 0.f); oA.y = fmaxf(oA.y, 0.f);
                oA.z = fmaxf(oA.z, 0.f); oA.w = fmaxf(oA.w, 0.f);
                oB.x = fmaxf(oB.x, 0.f); oB.y = fmaxf(oB.y, 0.f);
                oB.z = fmaxf(oB.z, 0.f); oB.w = fmaxf(oB.w, 0.f);
            }
            *(float4*)&O[(long)m * 128 + tx * 4] = oA;
            *(float4*)&O[(long)m * 128 + 64 + tx * 4] = oB;
        }
    }
}

// ---------------- GCN aggregation, width 128 (warp per node) ------------------
// out[i] = dis[i]*sum_e dis[src]*H[map(src)] + invdeg[i]*H[map(i)] + b   (opt relu)
__global__ void k_agg128(int srcid, int dstid, int g, const float* __restrict__ bias,
                         const int* __restrict__ map, int relu, int M)
{
    int lane = threadIdx.x & 31;
    int i = (blockIdx.x * blockDim.x + threadIdx.x) >> 5;
    if (i >= M) return;
    const float4* __restrict__ H4 = (const float4*)g_bufs[srcid];
    float4* __restrict__ O4 = (float4*)g_bufs[dstid];
    const float* __restrict__ dis = g_dis[g];
    const int* __restrict__ csr = g_csr[g];
    int s0 = g_off[g][i];
    int s1 = s0 + g_cnt[g][i];

    float4 acc = make_float4(0.f, 0.f, 0.f, 0.f);
    for (int e = s0; e < s1; e++) {
        int s = csr[e];
        float c = dis[s];
        int r = map ? map[s] : s;
        float4 h = H4[r * 32 + lane];
        acc.x = fmaf(c, h.x, acc.x);
        acc.y = fmaf(c, h.y, acc.y);
        acc.z = fmaf(c, h.z, acc.z);
        acc.w = fmaf(c, h.w, acc.w);
    }
    int rs = map ? map[i] : i;
    float4 hs = H4[rs * 32 + lane];
    float di = dis[i];
    float vd = g_invdeg[g][i];
    float4 b4 = ((const float4*)bias)[lane];
    float4 o;
    o.x = fmaf(di, acc.x, fmaf(vd, hs.x, b4.x));
    o.y = fmaf(di, acc.y, fmaf(vd, hs.y, b4.y));
    o.z = fmaf(di, acc.z, fmaf(vd, hs.z, b4.z));
    o.w = fmaf(di, acc.w, fmaf(vd, hs.w, b4.w));
    if (relu) {
        o.x = fmaxf(o.x, 0.f); o.y = fmaxf(o.y, 0.f);
        o.z = fmaxf(o.z, 0.f); o.w = fmaxf(o.w, 0.f);
    }
    O4[i * 32 + lane] = o;
}

// ---------------- classifier GEMM [NN,128]x[128,10] ---------------------------
__global__ __launch_bounds__(320) void k_gemm_n10(int xid, const float* __restrict__ W)
{
    __shared__ float sW[128 * 10];
    __shared__ float sX[32 * 128];
    int tid = threadIdx.x;
    const float* __restrict__ X = g_bufs[xid];
    for (int j = tid; j < 1280; j += 320) sW[j] = W[j];
    int m0 = blockIdx.x * 32;
    for (int j = tid; j < 32 * 128; j += 320) {
        int r = j >> 7, c = j & 127;
        int gm = m0 + r;
        sX[j] = (gm < NN) ? X[(long)gm * 128 + c] : 0.f;
    }
    __syncthreads();
    int lr = tid / 10, c = tid % 10;
    if (lr >= 32) return;
    int gm = m0 + lr;
    float acc = 0.f;
#pragma unroll 8
    for (int k = 0; k < 128; k++) acc = fmaf(sX[lr * 128 + k], sW[k * 10 + c], acc);
    if (gm < NN) g_Hc[gm * 10 + c] = acc;
}

// ---------------- classifier aggregation, width 10, into out[:,0:10] ----------
__global__ void k_agg10(float* __restrict__ out, const float* __restrict__ bc, int g, int M)
{
    int lane = threadIdx.x & 31;
    int i = (blockIdx.x * blockDim.x + threadIdx.x) >> 5;
    if (i >= M) return;
    const float* __restrict__ dis = g_dis[g];
    const int* __restrict__ csr = g_csr[g];
    int s0 = g_off[g][i];
    int s1 = s0 + g_cnt[g][i];
    float acc = 0.f;
    for (int e = s0; e < s1; e++) {
        int s = csr[e];
        float c = dis[s];
        float h = (lane < 10) ? g_Hc[s * 10 + lane] : 0.f;
        acc = fmaf(c, h, acc);
    }
    if (lane < 10) {
        float o = dis[i] * acc + g_invdeg[g][i] * g_Hc[i * 10 + lane] + bc[lane];
        out[(long)i * 12 + lane] = o;
    }
}

// ---------------- bilinear scores: sigmoid(rowdot(T, e2)) ---------------------
__global__ void k_score(int tbuf, int abuf, int bbuf, float* __restrict__ out, int M)
{
    int lane = threadIdx.x & 31;
    int i = (blockIdx.x * blockDim.x + threadIdx.x) >> 5;
    if (i >= M) return;
    float4 t = ((const float4*)g_bufs[tbuf])[i * 32 + lane];
    float4 a = ((const float4*)g_bufs[abuf])[i * 32 + lane];
    float4 b = ((const float4*)g_bufs[bbuf])[i * 32 + lane];
    float s1 = t.x * a.x + t.y * a.y + t.z * a.z + t.w * a.w;
    float s2 = t.x * b.x + t.y * b.y + t.z * b.z + t.w * b.w;
#pragma unroll
    for (int o = 16; o; o >>= 1) {
        s1 += __shfl_xor_sync(0xffffffffu, s1, o);
        s2 += __shfl_xor_sync(0xffffffffu, s2, o);
    }
    if (lane == 0) {
        out[(long)i * 12 + 10] = 1.f / (1.f + expf(-s1));
        out[(long)i * 12 + 11] = 1.f / (1.f + expf(-s2));
    }
}

// ---------------- launch ------------------------------------------------------
extern "C" void kernel_launch(void* const* d_in, const int* in_sizes, int n_in,
                              void* d_out, int out_size)
{
    const float* x    = (const float*)d_in[0];
    const int*   ei   = (const int*)d_in[1];
    const int*   eih  = (const int*)d_in[2];
    const int*   perm = (const int*)d_in[4];
    const float* W1 = (const float*)d_in[5];
    const float* b1 = (const float*)d_in[6];
    const float* W2 = (const float*)d_in[7];
    const float* b2 = (const float*)d_in[8];
    const float* W3 = (const float*)d_in[9];
    const float* b3 = (const float*)d_in[10];
    const float* M1 = (const float*)d_in[11];
    const float* mb1 = (const float*)d_in[12];
    const float* M2 = (const float*)d_in[13];
    const float* mb2 = (const float*)d_in[14];
    const float* Wc = (const float*)d_in[15];
    const float* bc = (const float*)d_in[16];
    const float* Wd = (const float*)d_in[17];
    float* out = (float*)d_out;

    int M = in_sizes[0] / 512;   // 100000
    int E = in_sizes[1] / 2;     // 1600000

    int nb_scan = (NN + 1023) / 1024;  // 98
    int GB = (M + 127) / 128;          // GEMM blocks (128-row tiles)
    int AB = (M + 7) / 8;              // agg blocks (8 warps/block)

    // --- CSR + degrees for both graphs ---
    k_zero_cnt<<<(NN + 255) / 256, 256>>>();
    k_count<<<(E + 255) / 256, 256>>>(ei, E, 0);
    k_count<<<(E + 255) / 256, 256>>>(eih, E, 1);
    k_deg<<<(NN + 255) / 256, 256>>>(0);
    k_deg<<<(NN + 255) / 256, 256>>>(1);
    k_scan1<<<nb_scan, 1024>>>(0);
    k_scan1<<<nb_scan, 1024>>>(1);
    k_scan2<<<1, 32>>>(0, nb_scan);
    k_scan2<<<1, 32>>>(1, nb_scan);
    k_scan3<<<(NN + 255) / 256, 256>>>(0);
    k_scan3<<<(NN + 255) / 256, 256>>>(1);
    k_fill<<<(E + 255) / 256, 256>>>(ei, E, 0);
    k_fill<<<(E + 255) / 256, 256>>>(eih, E, 1);

    // --- H = x @ W1 (shared by normal + permuted branch: x[perm]@W1 = H[perm]) ---
    k_gemm_n128<<<GB, 256>>>(x, -1, W1, 0, nullptr, 0, M, 512);

    // layer 1: h1 (buf1), h1_bad (buf2) via perm map
    k_agg128<<<AB, 256>>>(0, 1, 0, b1, nullptr, 1, M);
    k_agg128<<<AB, 256>>>(0, 2, 0, b1, perm, 1, M);

    // layer 2: embed1 (buf4), embed1_bad (buf5)
    k_gemm_n128<<<GB, 256>>>(nullptr, 1, W2, 3, nullptr, 0, M, 128);
    k_agg128<<<AB, 256>>>(3, 4, 0, b2, nullptr, 1, M);
    k_gemm_n128<<<GB, 256>>>(nullptr, 2, W2, 3, nullptr, 0, M, 128);
    k_agg128<<<AB, 256>>>(3, 5, 0, b2, nullptr, 1, M);

    // encoder2 (hop graph, no relu): embed2 (buf1), embed2_bad (buf2)
    k_gemm_n128<<<GB, 256>>>(nullptr, 4, W3, 0, nullptr, 0, M, 128);
    k_agg128<<<AB, 256>>>(0, 1, 1, b3, nullptr, 0, M);
    k_gemm_n128<<<GB, 256>>>(nullptr, 5, W3, 0, nullptr, 0, M, 128);
    k_agg128<<<AB, 256>>>(0, 2, 1, b3, nullptr, 0, M);

    // encoder3 MLP: embed3 = relu(embed1@M1+mb1)@M2+mb2  (buf0 tmp -> buf3)
    k_gemm_n128<<<GB, 256>>>(nullptr, 4, M1, 0, mb1, 1, M, 128);
    k_gemm_n128<<<GB, 256>>>(nullptr, 0, M2, 3, mb2, 0, M, 128);

    // bilinear: T = embed3 @ Wd (buf5), shared by both scores
    k_gemm_n128<<<GB, 256>>>(nullptr, 3, Wd, 5, nullptr, 0, M, 128);
    k_score<<<AB, 256>>>(5, 1, 2, out, M);

    // classifier: gcn(embed1, Wc) -> out[:,0:10]
    k_gemm_n10<<<(M + 31) / 32, 320>>>(4, Wc);
    k_agg10<<<AB, 256>>>(out, bc, 0, M);
}